// round 6
// baseline (speedup 1.0000x reference)
#include <cuda_runtime.h>

#define C_DIM    16
#define DIM_IN   16
#define XPAD     20          // floats per mu1 row in shared (80B stride, 16B-aligned)
#define MAX_NNZ  1024
#define MAX_GRP  1024
#define MAX_ROWS 256
#define MAX_PATHS 64

__device__ int   g_grp_start[MAX_ROWS + 1];   // CSR over GROUPS (unique (m3,mu1) pairs)
__device__ int   g_row_path[MAX_ROWS];
__device__ int   g_row_order[MAX_ROWS];       // rows sorted by group count desc
__device__ __align__(16) float  g_wT[MAX_PATHS * C_DIM];
// group: {cg_a, cg_b, pack = (mu1*80)<<8 | mu2_a<<4 | mu2_b, 0}; cg_b=0 if single
__device__ __align__(16) float4 g_groups[MAX_GRP];

// Prep (one block, 256 threads, fully parallel except a trivial 156-step prefix):
//  1. weight transpose; CSR row starts over globally-sorted mu_3; owning path/row
//  2. per-row grouping of entries by mu1 (<=2 entries share a (m3,mu1) pair)
//  3. group CSR + packed group table
//  4. parallel rank sort of rows by group count (desc) -> schedule
__global__ void tp_prep_kernel(const float* __restrict__ weights,
                               const float* __restrict__ cg,
                               const int* __restrict__ mu1,
                               const int* __restrict__ mu2,
                               const int* __restrict__ mu3,
                               const int* __restrict__ widx,
                               int nnz, int dim3v, int n_paths) {
    __shared__ int row_start_sh[MAX_ROWS + 1];
    __shared__ int cnt_sh[MAX_ROWS];
    __shared__ int grp_off_sh[MAX_ROWS + 1];
    const int t = threadIdx.x;

    for (int i = t; i < n_paths * C_DIM; i += blockDim.x) {
        int p = i >> 4, c = i & 15;
        g_wT[p * C_DIM + c] = weights[c * n_paths + p];
    }
    for (int m = t; m <= dim3v; m += blockDim.x) {
        int lo = 0, hi = nnz;
        while (lo < hi) {
            int mid = (lo + hi) >> 1;
            if (mu3[mid] < m) lo = mid + 1; else hi = mid;
        }
        row_start_sh[m] = lo;
        if (m < dim3v && lo < nnz) g_row_path[m] = widx[lo];
    }
    __syncthreads();

    // count groups per row
    for (int m = t; m < dim3v; m += blockDim.x) {
        int s = row_start_sh[m], en = row_start_sh[m + 1];
        int seen[16]; int ng = 0;
        for (int k = s; k < en; ++k) {
            int u = mu1[k];
            bool dup = false;
            for (int j = 0; j < ng; ++j) if (seen[j] == u) { dup = true; break; }
            if (!dup) seen[ng++] = u;
        }
        cnt_sh[m] = ng;
    }
    __syncthreads();

    if (t == 0) {
        int acc = 0;
        for (int m = 0; m < dim3v; ++m) { grp_off_sh[m] = acc; acc += cnt_sh[m]; }
        grp_off_sh[dim3v] = acc;
    }
    __syncthreads();

    for (int m = t; m <= dim3v; m += blockDim.x) g_grp_start[m] = grp_off_sh[m];

    // emit groups
    for (int m = t; m < dim3v; m += blockDim.x) {
        int s = row_start_sh[m], en = row_start_sh[m + 1];
        int base = grp_off_sh[m];
        int seen[16]; int gpos[16]; int ng = 0;
        for (int k = s; k < en; ++k) {
            int u = mu1[k];
            int g = -1;
            for (int j = 0; j < ng; ++j) if (seen[j] == u) { g = j; break; }
            if (g < 0) {
                g = ng; seen[ng] = u; gpos[ng] = base + ng; ng++;
                unsigned pack = ((unsigned)(u * (XPAD * 4)) << 8) | ((unsigned)mu2[k] << 4);
                g_groups[gpos[g]] = make_float4(cg[k], 0.f, __uint_as_float(pack), 0.f);
            } else {
                float4 v = g_groups[gpos[g]];
                unsigned pack = __float_as_uint(v.z) | (unsigned)mu2[k];
                g_groups[gpos[g]] = make_float4(v.x, cg[k], __uint_as_float(pack), 0.f);
            }
        }
    }
    __syncthreads();

    // rank rows by group count desc (stable)
    for (int m = t; m < dim3v; m += blockDim.x) {
        const int lm = cnt_sh[m];
        int rank = 0;
        for (int o = 0; o < dim3v; ++o) {
            int lo_ = cnt_sh[o];
            rank += (lo_ > lm) || (lo_ == lm && o < m);
        }
        g_row_order[rank] = m;
    }
}

// One block per edge, 256 threads: q = tid&3 -> channel quad, r = tid>>2 -> slot.
// Per-edge table: ent[j] = { cg_a*y[m2a] + cg_b*y[m2b], x byte-offset } per GROUP.
// Main loop per group: LDS.64 ent (quad-broadcast) + LDS.128 x + 4 FFMA.
__global__ void __launch_bounds__(256)
tp_main_kernel(const float* __restrict__ x,
               const float* __restrict__ y,
               float* __restrict__ out,
               int dim3v) {
    __shared__ __align__(16) float  x_sh[DIM_IN * XPAD];
    __shared__ __align__(8)  float2 ent_sh[MAX_GRP];

    const int e = blockIdx.x;
    const int t = threadIdx.x;
    const int n_groups = g_grp_start[dim3v];

    // stage x[e] : x[e][row][c] -> x_sh[row*XPAD + c]
    {
        float v = x[e * (DIM_IN * C_DIM) + t];
        x_sh[(t >> 4) * XPAD + (t & 15)] = v;
    }
    // build per-edge group table
    const float* ye = y + e * DIM_IN;
    for (int j = t; j < n_groups; j += 256) {
        float4 g = g_groups[j];
        unsigned pk = __float_as_uint(g.z);
        float cgy = g.x * __ldg(&ye[(pk >> 4) & 15u])
                  + g.y * __ldg(&ye[pk & 15u]);
        ent_sh[j] = make_float2(cgy, __uint_as_float(pk >> 8));
    }
    __syncthreads();

    const int q = t & 3;          // channel quad
    const int r = t >> 2;         // schedule slot 0..63
    const char* xb = (const char*)x_sh + q * 16;
    float* outE = out + (size_t)e * dim3v * C_DIM;

    for (int i = r; i < dim3v; i += 64) {
        const int m3 = g_row_order[i];
        const int s  = g_grp_start[m3];
        const int en = g_grp_start[m3 + 1];
        float4 acc = make_float4(0.f, 0.f, 0.f, 0.f);
        #pragma unroll 2
        for (int k = s; k < en; ++k) {
            float2 ent = ent_sh[k];
            const float4 xv = *(const float4*)(xb + __float_as_int(ent.y));
            acc.x = fmaf(xv.x, ent.x, acc.x);
            acc.y = fmaf(xv.y, ent.x, acc.y);
            acc.z = fmaf(xv.z, ent.x, acc.z);
            acc.w = fmaf(xv.w, ent.x, acc.w);
        }
        const float4 wv = *(const float4*)(g_wT + g_row_path[m3] * C_DIM + q * 4);
        acc.x *= wv.x; acc.y *= wv.y; acc.z *= wv.z; acc.w *= wv.w;
        *(float4*)(outE + m3 * C_DIM + q * 4) = acc;
    }
}

extern "C" void kernel_launch(void* const* d_in, const int* in_sizes, int n_in,
                              void* d_out, int out_size) {
    const float* x      = (const float*)d_in[0];
    const float* y      = (const float*)d_in[1];
    const float* cg     = (const float*)d_in[2];
    const float* w      = (const float*)d_in[3];
    const int*   mu1    = (const int*)d_in[4];
    const int*   mu2    = (const int*)d_in[5];
    const int*   mu3    = (const int*)d_in[6];
    const int*   widx   = (const int*)d_in[7];

    const int nnz     = in_sizes[4];
    const int E       = in_sizes[1] / DIM_IN;
    const int dim3v   = out_size / (E * C_DIM);
    const int n_paths = in_sizes[3] / C_DIM;

    tp_prep_kernel<<<1, 256>>>(w, cg, mu1, mu2, mu3, widx, nnz, dim3v, n_paths);
    tp_main_kernel<<<E, 256>>>(x, y, (float*)d_out, dim3v);
}

// round 8
// speedup vs baseline: 1.0052x; 1.0052x over previous
#include <cuda_runtime.h>

#define C_DIM    16
#define DIM_IN   16
#define XPAD     20          // floats per mu1 row in shared (80B stride, 16B-aligned)
#define MAX_NNZ  1024
#define MAX_GRP  1024
#define MAX_ROWS 256
#define MAX_PATHS 64

__device__ int   g_grp_start[MAX_ROWS + 1];   // CSR over GROUPS (unique (m3,mu1) pairs)
__device__ int   g_row_path[MAX_ROWS];
__device__ int   g_row_order[MAX_ROWS];       // rows sorted by group count desc
__device__ __align__(16) float  g_wT[MAX_PATHS * C_DIM];
// group: {cg_a, cg_b, pack = (mu1*80)<<8 | mu2_a<<4 | mu2_b, 0}; cg_b=0 if single
__device__ __align__(16) float4 g_groups[MAX_GRP];

// Prep (one block, 256 threads). ALL working state lives in shared memory so
// there are no long-latency global dependency chains: mu3 is staged to shared
// before the binary searches, and the group table is built (RMW'd) in shared
// and written to global once, coalesced.
__global__ void tp_prep_kernel(const float* __restrict__ weights,
                               const float* __restrict__ cg,
                               const int* __restrict__ mu1,
                               const int* __restrict__ mu2,
                               const int* __restrict__ mu3,
                               const int* __restrict__ widx,
                               int nnz, int dim3v, int n_paths) {
    __shared__ int mu3_sh[MAX_NNZ];
    __shared__ int row_start_sh[MAX_ROWS + 1];
    __shared__ int cnt_sh[MAX_ROWS];
    __shared__ int grp_off_sh[MAX_ROWS + 1];
    __shared__ __align__(16) float4 groups_sh[MAX_GRP];
    const int t = threadIdx.x;

    for (int k = t; k < nnz; k += blockDim.x) mu3_sh[k] = mu3[k];
    for (int i = t; i < n_paths * C_DIM; i += blockDim.x) {
        int p = i >> 4, c = i & 15;
        g_wT[p * C_DIM + c] = weights[c * n_paths + p];
    }
    __syncthreads();

    for (int m = t; m <= dim3v; m += blockDim.x) {
        int lo = 0, hi = nnz;
        while (lo < hi) {
            int mid = (lo + hi) >> 1;
            if (mu3_sh[mid] < m) lo = mid + 1; else hi = mid;
        }
        row_start_sh[m] = lo;
        if (m < dim3v && lo < nnz) g_row_path[m] = widx[lo];
    }
    __syncthreads();

    // count unique mu1 per row (groups)
    for (int m = t; m < dim3v; m += blockDim.x) {
        int s = row_start_sh[m], en = row_start_sh[m + 1];
        int seen[16]; int ng = 0;
        for (int k = s; k < en; ++k) {
            int u = mu1[k];
            bool dup = false;
            for (int j = 0; j < ng; ++j) if (seen[j] == u) { dup = true; break; }
            if (!dup) seen[ng++] = u;
        }
        cnt_sh[m] = ng;
    }
    __syncthreads();

    if (t == 0) {
        int acc = 0;
        for (int m = 0; m < dim3v; ++m) { grp_off_sh[m] = acc; acc += cnt_sh[m]; }
        grp_off_sh[dim3v] = acc;
    }
    __syncthreads();

    for (int m = t; m <= dim3v; m += blockDim.x) g_grp_start[m] = grp_off_sh[m];

    // emit groups into SHARED (cheap RMW), one row per thread
    for (int m = t; m < dim3v; m += blockDim.x) {
        int s = row_start_sh[m], en = row_start_sh[m + 1];
        int base = grp_off_sh[m];
        int seen[16]; int gpos[16]; int ng = 0;
        for (int k = s; k < en; ++k) {
            int u = mu1[k];
            int g = -1;
            for (int j = 0; j < ng; ++j) if (seen[j] == u) { g = j; break; }
            if (g < 0) {
                g = ng; seen[ng] = u; gpos[ng] = base + ng; ng++;
                unsigned pack = ((unsigned)(u * (XPAD * 4)) << 8) | ((unsigned)mu2[k] << 4);
                groups_sh[gpos[g]] = make_float4(cg[k], 0.f, __uint_as_float(pack), 0.f);
            } else {
                float4 v = groups_sh[gpos[g]];
                unsigned pack = __float_as_uint(v.z) | (unsigned)mu2[k];
                groups_sh[gpos[g]] = make_float4(v.x, cg[k], __uint_as_float(pack), 0.f);
            }
        }
    }
    __syncthreads();

    // single coalesced copy of the group table to global
    {
        const int n_groups = grp_off_sh[dim3v];
        for (int j = t; j < n_groups; j += blockDim.x) g_groups[j] = groups_sh[j];
    }

    // rank rows by group count desc (stable) -> schedule
    for (int m = t; m < dim3v; m += blockDim.x) {
        const int lm = cnt_sh[m];
        int rank = 0;
        for (int o = 0; o < dim3v; ++o) {
            int lo_ = cnt_sh[o];
            rank += (lo_ > lm) || (lo_ == lm && o < m);
        }
        g_row_order[rank] = m;
    }
}

// One block per edge, 256 threads: q = tid&3 -> channel quad, r = tid>>2 -> slot.
// Per-edge table: ent[j] = { cg_a*y[m2a] + cg_b*y[m2b], x byte-offset } per GROUP.
// Main loop per group: LDS.64 ent (quad-broadcast) + LDS.128 x + 4 FFMA.
__global__ void __launch_bounds__(256)
tp_main_kernel(const float* __restrict__ x,
               const float* __restrict__ y,
               float* __restrict__ out,
               int dim3v) {
    __shared__ __align__(16) float  x_sh[DIM_IN * XPAD];
    __shared__ __align__(8)  float2 ent_sh[MAX_GRP];

    const int e = blockIdx.x;
    const int t = threadIdx.x;
    const int n_groups = g_grp_start[dim3v];

    // stage x[e] : x[e][row][c] -> x_sh[row*XPAD + c]
    {
        float v = x[e * (DIM_IN * C_DIM) + t];
        x_sh[(t >> 4) * XPAD + (t & 15)] = v;
    }
    // build per-edge group table
    const float* ye = y + e * DIM_IN;
    for (int j = t; j < n_groups; j += 256) {
        float4 g = g_groups[j];
        unsigned pk = __float_as_uint(g.z);
        float cgy = g.x * __ldg(&ye[(pk >> 4) & 15u])
                  + g.y * __ldg(&ye[pk & 15u]);
        ent_sh[j] = make_float2(cgy, __uint_as_float(pk >> 8));
    }
    __syncthreads();

    const int q = t & 3;          // channel quad
    const int r = t >> 2;         // schedule slot 0..63
    const char* xb = (const char*)x_sh + q * 16;
    float* outE = out + (size_t)e * dim3v * C_DIM;

    for (int i = r; i < dim3v; i += 64) {
        const int m3 = g_row_order[i];
        const int s  = g_grp_start[m3];
        const int en = g_grp_start[m3 + 1];
        float4 acc = make_float4(0.f, 0.f, 0.f, 0.f);
        #pragma unroll 2
        for (int k = s; k < en; ++k) {
            float2 ent = ent_sh[k];
            const float4 xv = *(const float4*)(xb + __float_as_int(ent.y));
            acc.x = fmaf(xv.x, ent.x, acc.x);
            acc.y = fmaf(xv.y, ent.x, acc.y);
            acc.z = fmaf(xv.z, ent.x, acc.z);
            acc.w = fmaf(xv.w, ent.x, acc.w);
        }
        const float4 wv = *(const float4*)(g_wT + g_row_path[m3] * C_DIM + q * 4);
        acc.x *= wv.x; acc.y *= wv.y; acc.z *= wv.z; acc.w *= wv.w;
        *(float4*)(outE + m3 * C_DIM + q * 4) = acc;
    }
}

extern "C" void kernel_launch(void* const* d_in, const int* in_sizes, int n_in,
                              void* d_out, int out_size) {
    const float* x      = (const float*)d_in[0];
    const float* y      = (const float*)d_in[1];
    const float* cg     = (const float*)d_in[2];
    const float* w      = (const float*)d_in[3];
    const int*   mu1    = (const int*)d_in[4];
    const int*   mu2    = (const int*)d_in[5];
    const int*   mu3    = (const int*)d_in[6];
    const int*   widx   = (const int*)d_in[7];

    const int nnz     = in_sizes[4];
    const int E       = in_sizes[1] / DIM_IN;
    const int dim3v   = out_size / (E * C_DIM);
    const int n_paths = in_sizes[3] / C_DIM;

    tp_prep_kernel<<<1, 256>>>(w, cg, mu1, mu2, mu3, widx, nnz, dim3v, n_paths);
    tp_main_kernel<<<E, 256>>>(x, y, (float*)d_out, dim3v);
}

// round 9
// speedup vs baseline: 1.0506x; 1.0452x over previous
#include <cuda_runtime.h>

#define C_DIM    16
#define DIM_IN   16
#define XPAD     20          // floats per mu1 row in shared (80B stride, 16B-aligned)
#define MAX_NNZ  1024
#define MAX_GRP  1024
#define MAX_ROWS 256
#define MAX_PATHS 64

__device__ int   g_grp_start[MAX_ROWS + 1];   // CSR over GROUPS (unique (m3,mu1) pairs)
__device__ int   g_row_path[MAX_ROWS];
__device__ int   g_row_order[MAX_ROWS];       // rows sorted by group count desc
__device__ __align__(16) float  g_wT[MAX_PATHS * C_DIM];
// group: {cg_a, cg_b, pack = (mu1*80)<<8 | mu2_a<<4 | mu2_b, 0}; cg_b=0 if single
__device__ __align__(16) float4 g_groups[MAX_GRP];

// Prep (one block, 256 threads). ALL inputs are staged into shared first
// (coalesced) so every subsequent loop touches only shared memory; the group
// table is RMW'd in shared and written to global once, coalesced. Prefix sum
// over row group-counts is a warp scan (warp 0), not a serial thread-0 loop.
__global__ void tp_prep_kernel(const float* __restrict__ weights,
                               const float* __restrict__ cg,
                               const int* __restrict__ mu1,
                               const int* __restrict__ mu2,
                               const int* __restrict__ mu3,
                               const int* __restrict__ widx,
                               int nnz, int dim3v, int n_paths) {
    __shared__ int   mu3_sh[MAX_NNZ];
    __shared__ short mu1_sh[MAX_NNZ];
    __shared__ short mu2_sh[MAX_NNZ];
    __shared__ float cg_sh[MAX_NNZ];
    __shared__ int row_start_sh[MAX_ROWS + 1];
    __shared__ int cnt_sh[MAX_ROWS];
    __shared__ int grp_off_sh[MAX_ROWS + 1];
    __shared__ int scan_carry[8];
    __shared__ __align__(16) float4 groups_sh[MAX_GRP];
    const int t = threadIdx.x;

    for (int k = t; k < nnz; k += blockDim.x) {
        mu3_sh[k] = mu3[k];
        mu1_sh[k] = (short)mu1[k];
        mu2_sh[k] = (short)mu2[k];
        cg_sh[k]  = cg[k];
    }
    for (int i = t; i < n_paths * C_DIM; i += blockDim.x) {
        int p = i >> 4, c = i & 15;
        g_wT[p * C_DIM + c] = weights[c * n_paths + p];
    }
    __syncthreads();

    for (int m = t; m <= dim3v; m += blockDim.x) {
        int lo = 0, hi = nnz;
        while (lo < hi) {
            int mid = (lo + hi) >> 1;
            if (mu3_sh[mid] < m) lo = mid + 1; else hi = mid;
        }
        row_start_sh[m] = lo;
        if (m < dim3v && lo < nnz) g_row_path[m] = widx[lo];
    }
    __syncthreads();

    // count unique mu1 per row (groups) — all shared
    for (int m = t; m < dim3v; m += blockDim.x) {
        int s = row_start_sh[m], en = row_start_sh[m + 1];
        int seen[16]; int ng = 0;
        for (int k = s; k < en; ++k) {
            int u = mu1_sh[k];
            bool dup = false;
            for (int j = 0; j < ng; ++j) if (seen[j] == u) { dup = true; break; }
            if (!dup) seen[ng++] = u;
        }
        cnt_sh[m] = ng;
    }
    __syncthreads();

    // exclusive scan of cnt_sh[0..dim3v) with warp 0 (chunks of 32)
    if (t < 32) {
        int nchunk = (dim3v + 31) >> 5;
        int carry = 0;
        for (int cch = 0; cch < nchunk; ++cch) {
            int idx = (cch << 5) + t;
            int v = (idx < dim3v) ? cnt_sh[idx] : 0;
            // inclusive warp scan
            #pragma unroll
            for (int d = 1; d < 32; d <<= 1) {
                int n = __shfl_up_sync(0xffffffffu, v, d);
                if (t >= d) v += n;
            }
            if (idx <= dim3v) grp_off_sh[idx] = carry + v - ((idx < dim3v) ? cnt_sh[idx] : 0);
            carry += __shfl_sync(0xffffffffu, v, 31);
        }
        if (t == 0) grp_off_sh[dim3v] = carry;
    }
    __syncthreads();

    for (int m = t; m <= dim3v; m += blockDim.x) g_grp_start[m] = grp_off_sh[m];

    // emit groups into SHARED (cheap RMW), one row per thread — all shared
    for (int m = t; m < dim3v; m += blockDim.x) {
        int s = row_start_sh[m], en = row_start_sh[m + 1];
        int base = grp_off_sh[m];
        int seen[16]; int gpos[16]; int ng = 0;
        for (int k = s; k < en; ++k) {
            int u = mu1_sh[k];
            int g = -1;
            for (int j = 0; j < ng; ++j) if (seen[j] == u) { g = j; break; }
            if (g < 0) {
                g = ng; seen[ng] = u; gpos[ng] = base + ng; ng++;
                unsigned pack = ((unsigned)(u * (XPAD * 4)) << 8) | ((unsigned)mu2_sh[k] << 4);
                groups_sh[gpos[g]] = make_float4(cg_sh[k], 0.f, __uint_as_float(pack), 0.f);
            } else {
                float4 v = groups_sh[gpos[g]];
                unsigned pack = __float_as_uint(v.z) | (unsigned)mu2_sh[k];
                groups_sh[gpos[g]] = make_float4(v.x, cg_sh[k], __uint_as_float(pack), 0.f);
            }
        }
    }
    __syncthreads();

    // single coalesced copy of the group table to global (+1 zero pad entry
    // for the main kernel's software-pipelined lookahead)
    {
        const int n_groups = grp_off_sh[dim3v];
        for (int j = t; j < n_groups; j += blockDim.x) g_groups[j] = groups_sh[j];
        if (t == 0) g_groups[n_groups] = make_float4(0.f, 0.f, __uint_as_float(0u), 0.f);
    }

    // rank rows by group count desc (stable) -> schedule
    for (int m = t; m < dim3v; m += blockDim.x) {
        const int lm = cnt_sh[m];
        int rank = 0;
        for (int o = 0; o < dim3v; ++o) {
            int lo_ = cnt_sh[o];
            rank += (lo_ > lm) || (lo_ == lm && o < m);
        }
        g_row_order[rank] = m;
    }
}

// One block per edge, 256 threads: q = tid&3 -> channel quad, r = tid>>2 -> slot.
// Per-edge table: ent[j] = { cg_a*y[m2a] + cg_b*y[m2b], x byte-offset } per GROUP.
// Main loop is software-pipelined: the next group's ent is fetched while the
// current group's x row is being loaded/accumulated, hiding one LDS latency.
__global__ void __launch_bounds__(256)
tp_main_kernel(const float* __restrict__ x,
               const float* __restrict__ y,
               float* __restrict__ out,
               int dim3v) {
    __shared__ __align__(16) float  x_sh[DIM_IN * XPAD];
    __shared__ __align__(8)  float2 ent_sh[MAX_GRP + 1];

    const int e = blockIdx.x;
    const int t = threadIdx.x;
    const int n_groups = g_grp_start[dim3v];

    // stage x[e] : x[e][row][c] -> x_sh[row*XPAD + c]
    {
        float v = x[e * (DIM_IN * C_DIM) + t];
        x_sh[(t >> 4) * XPAD + (t & 15)] = v;
    }
    // build per-edge group table (+ pad entry for lookahead)
    const float* ye = y + e * DIM_IN;
    for (int j = t; j <= n_groups; j += 256) {
        float4 g = g_groups[j];
        unsigned pk = __float_as_uint(g.z);
        float cgy = g.x * __ldg(&ye[(pk >> 4) & 15u])
                  + g.y * __ldg(&ye[pk & 15u]);
        ent_sh[j] = make_float2(cgy, __uint_as_float(pk >> 8));
    }
    __syncthreads();

    const int q = t & 3;          // channel quad
    const int r = t >> 2;         // schedule slot 0..63
    const char* xb = (const char*)x_sh + q * 16;
    float* outE = out + (size_t)e * dim3v * C_DIM;

    for (int i = r; i < dim3v; i += 64) {
        const int m3 = g_row_order[i];
        const int s  = g_grp_start[m3];
        const int en = g_grp_start[m3 + 1];
        float4 acc = make_float4(0.f, 0.f, 0.f, 0.f);
        float2 ent = ent_sh[s];
        #pragma unroll 2
        for (int k = s; k < en; ++k) {
            float2 ent_n = ent_sh[k + 1];           // lookahead (pad-safe)
            const float4 xv = *(const float4*)(xb + __float_as_int(ent.y));
            acc.x = fmaf(xv.x, ent.x, acc.x);
            acc.y = fmaf(xv.y, ent.x, acc.y);
            acc.z = fmaf(xv.z, ent.x, acc.z);
            acc.w = fmaf(xv.w, ent.x, acc.w);
            ent = ent_n;
        }
        const float4 wv = *(const float4*)(g_wT + g_row_path[m3] * C_DIM + q * 4);
        acc.x *= wv.x; acc.y *= wv.y; acc.z *= wv.z; acc.w *= wv.w;
        *(float4*)(outE + m3 * C_DIM + q * 4) = acc;
    }
}

extern "C" void kernel_launch(void* const* d_in, const int* in_sizes, int n_in,
                              void* d_out, int out_size) {
    const float* x      = (const float*)d_in[0];
    const float* y      = (const float*)d_in[1];
    const float* cg     = (const float*)d_in[2];
    const float* w      = (const float*)d_in[3];
    const int*   mu1    = (const int*)d_in[4];
    const int*   mu2    = (const int*)d_in[5];
    const int*   mu3    = (const int*)d_in[6];
    const int*   widx   = (const int*)d_in[7];

    const int nnz     = in_sizes[4];
    const int E       = in_sizes[1] / DIM_IN;
    const int dim3v   = out_size / (E * C_DIM);
    const int n_paths = in_sizes[3] / C_DIM;

    tp_prep_kernel<<<1, 256>>>(w, cg, mu1, mu2, mu3, widx, nnz, dim3v, n_paths);
    tp_main_kernel<<<E, 256>>>(x, y, (float*)d_out, dim3v);
}

// round 10
// speedup vs baseline: 1.1130x; 1.0594x over previous
#include <cuda_runtime.h>

#define C_DIM    16
#define DIM_IN   16
#define XPAD     20          // floats per mu1 row in shared (80B stride, 16B-aligned)
#define MAX_NNZ  1024
#define MAX_GRP  1024
#define MAX_ROWS 256
#define MAX_PATHS 64

__device__ int   g_grp_start[MAX_ROWS + 1];   // CSR over GROUPS (unique (m3,mu1) pairs)
__device__ int   g_row_path[MAX_ROWS];
__device__ int   g_row_order[MAX_ROWS];       // rows sorted by group count desc
__device__ __align__(16) float  g_wT[MAX_PATHS * C_DIM];
// group: {cg_a, cg_b, pack = (mu1*80)<<8 | mu2_a<<4 | mu2_b, 0}; cg_b=0 if single
__device__ __align__(16) float4 g_groups[MAX_GRP];

// Prep (one block, 256 threads). ALL inputs staged into shared (coalesced);
// group table RMW'd in shared, written to global once. Warp-scan prefix.
// Signals PDL completion as soon as all global outputs are written.
__global__ void tp_prep_kernel(const float* __restrict__ weights,
                               const float* __restrict__ cg,
                               const int* __restrict__ mu1,
                               const int* __restrict__ mu2,
                               const int* __restrict__ mu3,
                               const int* __restrict__ widx,
                               int nnz, int dim3v, int n_paths) {
    __shared__ int   mu3_sh[MAX_NNZ];
    __shared__ short mu1_sh[MAX_NNZ];
    __shared__ short mu2_sh[MAX_NNZ];
    __shared__ float cg_sh[MAX_NNZ];
    __shared__ int row_start_sh[MAX_ROWS + 1];
    __shared__ int cnt_sh[MAX_ROWS];
    __shared__ int grp_off_sh[MAX_ROWS + 1];
    __shared__ __align__(16) float4 groups_sh[MAX_GRP];
    const int t = threadIdx.x;

    for (int k = t; k < nnz; k += blockDim.x) {
        mu3_sh[k] = mu3[k];
        mu1_sh[k] = (short)mu1[k];
        mu2_sh[k] = (short)mu2[k];
        cg_sh[k]  = cg[k];
    }
    for (int i = t; i < n_paths * C_DIM; i += blockDim.x) {
        int p = i >> 4, c = i & 15;
        g_wT[p * C_DIM + c] = weights[c * n_paths + p];
    }
    __syncthreads();

    for (int m = t; m <= dim3v; m += blockDim.x) {
        int lo = 0, hi = nnz;
        while (lo < hi) {
            int mid = (lo + hi) >> 1;
            if (mu3_sh[mid] < m) lo = mid + 1; else hi = mid;
        }
        row_start_sh[m] = lo;
        if (m < dim3v && lo < nnz) g_row_path[m] = widx[lo];
    }
    __syncthreads();

    // count unique mu1 per row (groups) — all shared
    for (int m = t; m < dim3v; m += blockDim.x) {
        int s = row_start_sh[m], en = row_start_sh[m + 1];
        int seen[16]; int ng = 0;
        for (int k = s; k < en; ++k) {
            int u = mu1_sh[k];
            bool dup = false;
            for (int j = 0; j < ng; ++j) if (seen[j] == u) { dup = true; break; }
            if (!dup) seen[ng++] = u;
        }
        cnt_sh[m] = ng;
    }
    __syncthreads();

    // exclusive scan of cnt_sh[0..dim3v) with warp 0 (chunks of 32)
    if (t < 32) {
        int nchunk = (dim3v + 31) >> 5;
        int carry = 0;
        for (int cch = 0; cch < nchunk; ++cch) {
            int idx = (cch << 5) + t;
            int v = (idx < dim3v) ? cnt_sh[idx] : 0;
            #pragma unroll
            for (int d = 1; d < 32; d <<= 1) {
                int n = __shfl_up_sync(0xffffffffu, v, d);
                if (t >= d) v += n;
            }
            if (idx <= dim3v) grp_off_sh[idx] = carry + v - ((idx < dim3v) ? cnt_sh[idx] : 0);
            carry += __shfl_sync(0xffffffffu, v, 31);
        }
        if (t == 0) grp_off_sh[dim3v] = carry;
    }
    __syncthreads();

    for (int m = t; m <= dim3v; m += blockDim.x) g_grp_start[m] = grp_off_sh[m];

    // emit groups into SHARED (cheap RMW), one row per thread — all shared
    for (int m = t; m < dim3v; m += blockDim.x) {
        int s = row_start_sh[m], en = row_start_sh[m + 1];
        int base = grp_off_sh[m];
        int seen[16]; int gpos[16]; int ng = 0;
        for (int k = s; k < en; ++k) {
            int u = mu1_sh[k];
            int g = -1;
            for (int j = 0; j < ng; ++j) if (seen[j] == u) { g = j; break; }
            if (g < 0) {
                g = ng; seen[ng] = u; gpos[ng] = base + ng; ng++;
                unsigned pack = ((unsigned)(u * (XPAD * 4)) << 8) | ((unsigned)mu2_sh[k] << 4);
                groups_sh[gpos[g]] = make_float4(cg_sh[k], 0.f, __uint_as_float(pack), 0.f);
            } else {
                float4 v = groups_sh[gpos[g]];
                unsigned pack = __float_as_uint(v.z) | (unsigned)mu2_sh[k];
                groups_sh[gpos[g]] = make_float4(v.x, cg_sh[k], __uint_as_float(pack), 0.f);
            }
        }
    }
    __syncthreads();

    // group table to global (+1 zero pad entry for the lookahead)
    {
        const int n_groups = grp_off_sh[dim3v];
        for (int j = t; j < n_groups; j += blockDim.x) g_groups[j] = groups_sh[j];
        if (t == 0) g_groups[n_groups] = make_float4(0.f, 0.f, __uint_as_float(0u), 0.f);
    }

    // rank rows by group count desc (stable) -> schedule
    for (int m = t; m < dim3v; m += blockDim.x) {
        const int lm = cnt_sh[m];
        int rank = 0;
        for (int o = 0; o < dim3v; ++o) {
            int lo_ = cnt_sh[o];
            rank += (lo_ > lm) || (lo_ == lm && o < m);
        }
        g_row_order[rank] = m;
    }

    // all global outputs written -> release the dependent main launch
    __syncthreads();
    cudaTriggerProgrammaticLaunchCompletion();
}

// One block per edge, 256 threads: q = tid&3 -> channel quad, r = tid>>2 -> slot.
// PDL: the x/y staging preamble runs while the prep kernel is still finishing;
// cudaGridDependencySynchronize() gates the first read of prep outputs.
// Main loop: software-pipelined ent fetch + LDS.128 x + 4 FFMA per group.
__global__ void __launch_bounds__(256)
tp_main_kernel(const float* __restrict__ x,
               const float* __restrict__ y,
               float* __restrict__ out,
               int dim3v) {
    __shared__ __align__(16) float  x_sh[DIM_IN * XPAD];
    __shared__ __align__(8)  float2 ent_sh[MAX_GRP + 1];
    __shared__ float y_sh[DIM_IN];

    const int e = blockIdx.x;
    const int t = threadIdx.x;

    // ---- preamble (independent of prep outputs) ----
    {
        float v = x[e * (DIM_IN * C_DIM) + t];
        x_sh[(t >> 4) * XPAD + (t & 15)] = v;
        if (t < DIM_IN) y_sh[t] = y[e * DIM_IN + t];
    }

    cudaGridDependencySynchronize();       // wait for prep's global writes
    __syncthreads();                       // y_sh/x_sh visible block-wide

    const int n_groups = g_grp_start[dim3v];

    // build per-edge group table (+ pad entry for lookahead)
    for (int j = t; j <= n_groups; j += 256) {
        float4 g = g_groups[j];
        unsigned pk = __float_as_uint(g.z);
        float cgy = g.x * y_sh[(pk >> 4) & 15u]
                  + g.y * y_sh[pk & 15u];
        ent_sh[j] = make_float2(cgy, __uint_as_float(pk >> 8));
    }
    __syncthreads();

    const int q = t & 3;          // channel quad
    const int r = t >> 2;         // schedule slot 0..63
    const char* xb = (const char*)x_sh + q * 16;
    float* outE = out + (size_t)e * dim3v * C_DIM;

    for (int i = r; i < dim3v; i += 64) {
        const int m3 = g_row_order[i];
        const int s  = g_grp_start[m3];
        const int en = g_grp_start[m3 + 1];
        float4 acc = make_float4(0.f, 0.f, 0.f, 0.f);
        float2 ent = ent_sh[s];
        #pragma unroll 2
        for (int k = s; k < en; ++k) {
            float2 ent_n = ent_sh[k + 1];           // lookahead (pad-safe)
            const float4 xv = *(const float4*)(xb + __float_as_int(ent.y));
            acc.x = fmaf(xv.x, ent.x, acc.x);
            acc.y = fmaf(xv.y, ent.x, acc.y);
            acc.z = fmaf(xv.z, ent.x, acc.z);
            acc.w = fmaf(xv.w, ent.x, acc.w);
            ent = ent_n;
        }
        const float4 wv = *(const float4*)(g_wT + g_row_path[m3] * C_DIM + q * 4);
        acc.x *= wv.x; acc.y *= wv.y; acc.z *= wv.z; acc.w *= wv.w;
        *(float4*)(outE + m3 * C_DIM + q * 4) = acc;
    }
}

extern "C" void kernel_launch(void* const* d_in, const int* in_sizes, int n_in,
                              void* d_out, int out_size) {
    const float* x      = (const float*)d_in[0];
    const float* y      = (const float*)d_in[1];
    const float* cg     = (const float*)d_in[2];
    const float* w      = (const float*)d_in[3];
    const int*   mu1    = (const int*)d_in[4];
    const int*   mu2    = (const int*)d_in[5];
    const int*   mu3    = (const int*)d_in[6];
    const int*   widx   = (const int*)d_in[7];

    const int nnz     = in_sizes[4];
    const int E       = in_sizes[1] / DIM_IN;
    const int dim3v   = out_size / (E * C_DIM);
    const int n_paths = in_sizes[3] / C_DIM;

    tp_prep_kernel<<<1, 256>>>(w, cg, mu1, mu2, mu3, widx, nnz, dim3v, n_paths);

    // main kernel launched with Programmatic Dependent Launch so its grid
    // ramp + x/y staging overlap the prep kernel's tail
    cudaLaunchConfig_t cfg = {};
    cfg.gridDim  = dim3(E);
    cfg.blockDim = dim3(256);
    cudaLaunchAttribute attrs[1];
    attrs[0].id = cudaLaunchAttributeProgrammaticStreamSerialization;
    attrs[0].val.programmaticStreamSerializationAllowed = 1;
    cfg.attrs = attrs;
    cfg.numAttrs = 1;
    cudaLaunchKernelEx(&cfg, tp_main_kernel, x, y, (float*)d_out, dim3v);
}

// round 12
// speedup vs baseline: 1.1962x; 1.0748x over previous
#include <cuda_runtime.h>

#define C_DIM    16
#define DIM_IN   16
#define XPAD     20          // floats per mu1 row in shared (80B stride, 16B-aligned)
#define MAX_NNZ  1024
#define MAX_GRP  1024
#define MAX_ROWS 256
#define MAX_PATHS 64

__device__ int   g_grp_start[MAX_ROWS + 1];   // CSR over GROUPS (unique (m3,mu1) pairs)
__device__ int   g_row_path[MAX_ROWS];
__device__ int   g_row_order[MAX_ROWS];       // rows sorted by group count desc
__device__ __align__(16) float  g_wT[MAX_PATHS * C_DIM];
// group: {cg_a, cg_b, pack = (mu1*80)<<8 | mu2_a<<4 | mu2_b, 0}; cg_b=0 if single
__device__ __align__(16) float4 g_groups[MAX_GRP];

__device__ __forceinline__ unsigned s2u(const void* p) {
    return (unsigned)__cvta_generic_to_shared(p);
}

// Prep (one block, 256 threads). Row starts come from a first-occurrence
// scatter over the globally-sorted mu3 (no binary search, no latency chains).
// Group table RMW'd in shared, written to global once. Warp-scan prefix.
__global__ void tp_prep_kernel(const float* __restrict__ weights,
                               const float* __restrict__ cg,
                               const int* __restrict__ mu1,
                               const int* __restrict__ mu2,
                               const int* __restrict__ mu3,
                               const int* __restrict__ widx,
                               int nnz, int dim3v, int n_paths) {
    __shared__ short mu1_sh[MAX_NNZ];
    __shared__ short mu2_sh[MAX_NNZ];
    __shared__ float cg_sh[MAX_NNZ];
    __shared__ int row_start_sh[MAX_ROWS + 1];
    __shared__ int cnt_sh[MAX_ROWS];
    __shared__ int grp_off_sh[MAX_ROWS + 1];
    __shared__ __align__(16) float4 groups_sh[MAX_GRP];
    const int t = threadIdx.x;

    // stage small arrays + scatter row starts (every row is non-empty by the
    // CG selection rule, and mu3 is globally non-decreasing)
    for (int k = t; k < nnz; k += blockDim.x) {
        mu1_sh[k] = (short)mu1[k];
        mu2_sh[k] = (short)mu2[k];
        cg_sh[k]  = cg[k];
        int m = mu3[k];
        if (k == 0 || mu3[k - 1] != m) row_start_sh[m] = k;
    }
    for (int i = t; i < n_paths * C_DIM; i += blockDim.x) {
        int p = i >> 4, c = i & 15;
        g_wT[p * C_DIM + c] = weights[c * n_paths + p];
    }
    if (t == 0) row_start_sh[dim3v] = nnz;
    __syncthreads();

    // owning path per row + group counting (unique mu1 per row) — all shared
    for (int m = t; m < dim3v; m += blockDim.x) {
        g_row_path[m] = widx[row_start_sh[m]];
        int s = row_start_sh[m], en = row_start_sh[m + 1];
        int seen[16]; int ng = 0;
        for (int k = s; k < en; ++k) {
            int u = mu1_sh[k];
            bool dup = false;
            for (int j = 0; j < ng; ++j) if (seen[j] == u) { dup = true; break; }
            if (!dup) seen[ng++] = u;
        }
        cnt_sh[m] = ng;
    }
    __syncthreads();

    // exclusive scan of cnt_sh[0..dim3v) with warp 0 (chunks of 32)
    if (t < 32) {
        int nchunk = (dim3v + 31) >> 5;
        int carry = 0;
        for (int cch = 0; cch < nchunk; ++cch) {
            int idx = (cch << 5) + t;
            int v = (idx < dim3v) ? cnt_sh[idx] : 0;
            #pragma unroll
            for (int d = 1; d < 32; d <<= 1) {
                int n = __shfl_up_sync(0xffffffffu, v, d);
                if (t >= d) v += n;
            }
            if (idx <= dim3v) grp_off_sh[idx] = carry + v - ((idx < dim3v) ? cnt_sh[idx] : 0);
            carry += __shfl_sync(0xffffffffu, v, 31);
        }
        if (t == 0) grp_off_sh[dim3v] = carry;
    }
    __syncthreads();

    for (int m = t; m <= dim3v; m += blockDim.x) g_grp_start[m] = grp_off_sh[m];

    // emit groups into SHARED (cheap RMW), one row per thread — all shared
    for (int m = t; m < dim3v; m += blockDim.x) {
        int s = row_start_sh[m], en = row_start_sh[m + 1];
        int base = grp_off_sh[m];
        int seen[16]; int gpos[16]; int ng = 0;
        for (int k = s; k < en; ++k) {
            int u = mu1_sh[k];
            int g = -1;
            for (int j = 0; j < ng; ++j) if (seen[j] == u) { g = j; break; }
            if (g < 0) {
                g = ng; seen[ng] = u; gpos[ng] = base + ng; ng++;
                unsigned pack = ((unsigned)(u * (XPAD * 4)) << 8) | ((unsigned)mu2_sh[k] << 4);
                groups_sh[gpos[g]] = make_float4(cg_sh[k], 0.f, __uint_as_float(pack), 0.f);
            } else {
                float4 v = groups_sh[gpos[g]];
                unsigned pack = __float_as_uint(v.z) | (unsigned)mu2_sh[k];
                groups_sh[gpos[g]] = make_float4(v.x, cg_sh[k], __uint_as_float(pack), 0.f);
            }
        }
    }
    __syncthreads();

    // group table to global (+1 zero pad entry for the lookahead)
    {
        const int n_groups = grp_off_sh[dim3v];
        for (int j = t; j < n_groups; j += blockDim.x) g_groups[j] = groups_sh[j];
        if (t == 0) g_groups[n_groups] = make_float4(0.f, 0.f, __uint_as_float(0u), 0.f);
    }

    // rank rows by group count desc (stable) -> schedule
    for (int m = t; m < dim3v; m += blockDim.x) {
        const int lm = cnt_sh[m];
        int rank = 0;
        for (int o = 0; o < dim3v; ++o) {
            int lo_ = cnt_sh[o];
            rank += (lo_ > lm) || (lo_ == lm && o < m);
        }
        g_row_order[rank] = m;
    }

    // all global outputs written -> release the dependent main launch
    __syncthreads();
    cudaTriggerProgrammaticLaunchCompletion();
}

// One block per edge, 256 threads: q = tid&3 -> channel quad, r = tid>>2 -> slot.
// PDL preamble overlaps prep. Inner loop uses packed f32x2 math:
//   ld.shared.v2.u64 (x row -> 2 packed regs), mov.b64 splat of cgy,
//   2x fma.rn.f32x2; epilogue 2x mul.rn.f32x2 + st.global.cs.v2.u64.
__global__ void __launch_bounds__(256)
tp_main_kernel(const float* __restrict__ x,
               const float* __restrict__ y,
               float* __restrict__ out,
               int dim3v) {
    __shared__ __align__(16) float  x_sh[DIM_IN * XPAD];
    __shared__ __align__(8)  float2 ent_sh[MAX_GRP + 1];
    __shared__ float y_sh[DIM_IN];

    const int e = blockIdx.x;
    const int t = threadIdx.x;

    // ---- preamble (independent of prep outputs) ----
    {
        float v = x[e * (DIM_IN * C_DIM) + t];
        x_sh[(t >> 4) * XPAD + (t & 15)] = v;
        if (t < DIM_IN) y_sh[t] = y[e * DIM_IN + t];
    }

    cudaGridDependencySynchronize();       // wait for prep's global writes
    __syncthreads();                       // y_sh/x_sh visible block-wide

    const int n_groups = g_grp_start[dim3v];

    // build per-edge group table (+ pad entry for lookahead)
    for (int j = t; j <= n_groups; j += 256) {
        float4 g = g_groups[j];
        unsigned pk = __float_as_uint(g.z);
        float cgy = g.x * y_sh[(pk >> 4) & 15u]
                  + g.y * y_sh[pk & 15u];
        ent_sh[j] = make_float2(cgy, __uint_as_float(pk >> 8));
    }
    __syncthreads();

    const int q = t & 3;          // channel quad
    const int r = t >> 2;         // schedule slot 0..63
    const unsigned xq = s2u(x_sh) + (unsigned)(q * 16);
    float* outE = out + (size_t)e * dim3v * C_DIM;

    for (int i = r; i < dim3v; i += 64) {
        const int m3 = g_row_order[i];
        const int s  = g_grp_start[m3];
        const int en = g_grp_start[m3 + 1];

        unsigned long long acc01 = 0ull, acc23 = 0ull;   // {0.f,0.f} packed
        float2 ent = ent_sh[s];
        #pragma unroll 2
        for (int k = s; k < en; ++k) {
            float2 ent_n = ent_sh[k + 1];                // lookahead (pad-safe)
            unsigned long long x01, x23, c2;
            asm volatile("ld.shared.v2.u64 {%0,%1},[%2];"
                         : "=l"(x01), "=l"(x23)
                         : "r"(xq + __float_as_uint(ent.y)));
            asm("mov.b64 %0,{%1,%1};" : "=l"(c2) : "f"(ent.x));
            asm("fma.rn.f32x2 %0,%1,%2,%0;" : "+l"(acc01) : "l"(x01), "l"(c2));
            asm("fma.rn.f32x2 %0,%1,%2,%0;" : "+l"(acc23) : "l"(x23), "l"(c2));
            ent = ent_n;
        }

        const float4 wv = *(const float4*)(g_wT + g_row_path[m3] * C_DIM + q * 4);
        unsigned long long w01, w23;
        asm("mov.b64 %0,{%1,%2};" : "=l"(w01) : "f"(wv.x), "f"(wv.y));
        asm("mov.b64 %0,{%1,%2};" : "=l"(w23) : "f"(wv.z), "f"(wv.w));
        asm("mul.rn.f32x2 %0,%0,%1;" : "+l"(acc01) : "l"(w01));
        asm("mul.rn.f32x2 %0,%0,%1;" : "+l"(acc23) : "l"(w23));

        float* dst = outE + m3 * C_DIM + q * 4;
        asm volatile("st.global.cs.v2.u64 [%0],{%1,%2};"
                     :: "l"(dst), "l"(acc01), "l"(acc23) : "memory");
    }
}

extern "C" void kernel_launch(void* const* d_in, const int* in_sizes, int n_in,
                              void* d_out, int out_size) {
    const float* x      = (const float*)d_in[0];
    const float* y      = (const float*)d_in[1];
    const float* cg     = (const float*)d_in[2];
    const float* w      = (const float*)d_in[3];
    const int*   mu1    = (const int*)d_in[4];
    const int*   mu2    = (const int*)d_in[5];
    const int*   mu3    = (const int*)d_in[6];
    const int*   widx   = (const int*)d_in[7];

    const int nnz     = in_sizes[4];
    const int E       = in_sizes[1] / DIM_IN;
    const int dim3v   = out_size / (E * C_DIM);
    const int n_paths = in_sizes[3] / C_DIM;

    tp_prep_kernel<<<1, 256>>>(w, cg, mu1, mu2, mu3, widx, nnz, dim3v, n_paths);

    // main kernel launched with Programmatic Dependent Launch so its grid
    // ramp + x/y staging overlap the prep kernel's tail
    cudaLaunchConfig_t cfg = {};
    cfg.gridDim  = dim3(E);
    cfg.blockDim = dim3(256);
    cudaLaunchAttribute attrs[1];
    attrs[0].id = cudaLaunchAttributeProgrammaticStreamSerialization;
    attrs[0].val.programmaticStreamSerializationAllowed = 1;
    cfg.attrs = attrs;
    cfg.numAttrs = 1;
    cudaLaunchKernelEx(&cfg, tp_main_kernel, x, y, (float*)d_out, dim3v);
}

// round 16
// speedup vs baseline: 1.2363x; 1.0335x over previous
#include <cuda_runtime.h>

#define C_DIM    16
#define DIM_IN   16
#define XPAD     20          // floats per mu1 row in shared (80B stride, 16B-aligned)
#define MAX_NNZ  1024
#define MAX_GRP  1024
#define MAX_ROWS 256
#define MAX_JOBS 160
#define MAX_PATHS 64

// job = fused (+m, -m) row pair within a path (or m=0 singleton).
__device__ int   g_job_start[MAX_JOBS + 1];   // CSR over pair-groups per job
__device__ int   g_job_info[MAX_JOBS];        // rowA | rowB<<8 | path<<16
__device__ int   g_job_order[MAX_JOBS];       // jobs sorted by group count desc
__device__ int2  g_counts;                    // {njobs, n_pair_groups}
__device__ __align__(16) float  g_wT[MAX_PATHS * C_DIM];
// pair-group statics: cg4 = {cgA_a, cgA_b, cgB_a, cgB_b},
// pack = (mu1*80)<<8 | m2a<<4 | m2b   (unused slots have cg = 0)
__device__ __align__(16) float4   g_cg4[MAX_GRP + 1];
__device__ unsigned g_pack[MAX_GRP + 1];

__device__ __forceinline__ unsigned s2u(const void* p) {
    return (unsigned)__cvta_generic_to_shared(p);
}

// Prep (one block, 256 threads). Builds the paired-row job structure:
//  - row starts by first-occurrence scatter over sorted mu3
//  - path extents from the contiguous widx blocks
//  - jobs pair row i with row d3-1-i inside each path (identical (m1,m2)
//    support by the |m1+m2|==|m3| selection rule; only cg differs)
//  - per job: unique-mu1 groups from rowA, rowB's cg matched into the slots
__global__ void tp_prep_kernel(const float* __restrict__ weights,
                               const float* __restrict__ cg,
                               const int* __restrict__ mu1,
                               const int* __restrict__ mu2,
                               const int* __restrict__ mu3,
                               const int* __restrict__ widx,
                               int nnz, int dim3v, int n_paths) {
    __shared__ short mu1_sh[MAX_NNZ];
    __shared__ short mu2_sh[MAX_NNZ];
    __shared__ float cg_sh[MAX_NNZ];
    __shared__ int row_start_sh[MAX_ROWS + 1];
    __shared__ int row_path_sh[MAX_ROWS];
    __shared__ int path_first_sh[MAX_PATHS + 1];
    __shared__ int jobid_sh[MAX_ROWS];        // job id per leader row
    __shared__ int job_cnt[MAX_JOBS];
    __shared__ int job_off[MAX_JOBS + 1];
    __shared__ int njobs_sh;
    __shared__ __align__(16) float4   cg4_sh[MAX_GRP];
    __shared__ unsigned pack_sh[MAX_GRP];
    const int t = threadIdx.x;

    for (int k = t; k < nnz; k += blockDim.x) {
        mu1_sh[k] = (short)mu1[k];
        mu2_sh[k] = (short)mu2[k];
        cg_sh[k]  = cg[k];
        int m = mu3[k];
        if (k == 0 || mu3[k - 1] != m) row_start_sh[m] = k;
    }
    for (int i = t; i < n_paths * C_DIM; i += blockDim.x) {
        int p = i >> 4, c = i & 15;
        g_wT[p * C_DIM + c] = weights[c * n_paths + p];
    }
    if (t == 0) row_start_sh[dim3v] = nnz;
    __syncthreads();

    for (int m = t; m < dim3v; m += blockDim.x)
        row_path_sh[m] = widx[row_start_sh[m]];
    __syncthreads();

    for (int m = t; m < dim3v; m += blockDim.x) {
        int p = row_path_sh[m];
        if (m == 0 || row_path_sh[m - 1] != p) path_first_sh[p] = m;
    }
    if (t == 0) path_first_sh[n_paths] = dim3v;
    __syncthreads();

    // leader flags (row is job leader if its in-path index i <= d3-1-i) and
    // exclusive scan -> job ids (warp 0)
    if (t < 32) {
        int nchunk = (dim3v + 31) >> 5;
        int carry = 0;
        for (int cch = 0; cch < nchunk; ++cch) {
            int idx = (cch << 5) + t;
            int f = 0;
            if (idx < dim3v) {
                int p = row_path_sh[idx];
                int pf = path_first_sh[p];
                int d3 = path_first_sh[p + 1] - pf;
                f = (2 * (idx - pf) <= d3 - 1);
            }
            int v = f;
            #pragma unroll
            for (int d = 1; d < 32; d <<= 1) {
                int n = __shfl_up_sync(0xffffffffu, v, d);
                if (t >= d) v += n;
            }
            if (idx < dim3v) jobid_sh[idx] = (carry + v - f) | (f ? 0 : 0x40000000);
            carry += __shfl_sync(0xffffffffu, v, 31);
        }
        if (t == 0) njobs_sh = carry;
    }
    __syncthreads();
    const int njobs = njobs_sh;

    // count unique mu1 per leader row -> job group counts
    for (int m = t; m < dim3v; m += blockDim.x) {
        int jid = jobid_sh[m];
        if (jid & 0x40000000) continue;               // not a leader
        int s = row_start_sh[m], en = row_start_sh[m + 1];
        int seen[8]; int ng = 0;
        for (int k = s; k < en; ++k) {
            int u = mu1_sh[k];
            bool dup = false;
            for (int j = 0; j < ng; ++j) if (seen[j] == u) { dup = true; break; }
            if (!dup) seen[ng++] = u;
        }
        job_cnt[jid] = ng;
    }
    __syncthreads();

    // exclusive scan of job_cnt (warp 0)
    if (t < 32) {
        int nchunk = (njobs + 31) >> 5;
        int carry = 0;
        for (int cch = 0; cch < nchunk; ++cch) {
            int idx = (cch << 5) + t;
            int v = (idx < njobs) ? job_cnt[idx] : 0;
            #pragma unroll
            for (int d = 1; d < 32; d <<= 1) {
                int n = __shfl_up_sync(0xffffffffu, v, d);
                if (t >= d) v += n;
            }
            if (idx < njobs) job_off[idx] = carry + v - job_cnt[idx];
            carry += __shfl_sync(0xffffffffu, v, 31);
        }
        if (t == 0) job_off[njobs] = carry;
    }
    __syncthreads();

    // emit pair-groups: rowA builds the slots, rowB's cgs matched in
    for (int m = t; m < dim3v; m += blockDim.x) {
        int jid = jobid_sh[m];
        if (jid & 0x40000000) continue;
        int p  = row_path_sh[m];
        int pf = path_first_sh[p];
        int d3 = path_first_sh[p + 1] - pf;
        int rowB = pf + (d3 - 1) - (m - pf);
        int s = row_start_sh[m], en = row_start_sh[m + 1];

        short uA[8], m2A[8], m2B[8];
        float cAa[8], cAb[8], cBa[8], cBb[8];
        int ng = 0;
        for (int k = s; k < en; ++k) {
            int u = mu1_sh[k], v = mu2_sh[k];
            float c = cg_sh[k];
            int g = -1;
            for (int j = 0; j < ng; ++j) if (uA[j] == u) { g = j; break; }
            if (g < 0) {
                g = ng++;
                uA[g] = (short)u; m2A[g] = (short)v; m2B[g] = 0;
                cAa[g] = c; cAb[g] = 0.f; cBa[g] = 0.f; cBb[g] = 0.f;
            } else {
                m2B[g] = (short)v; cAb[g] = c;
            }
        }
        if (rowB != m) {
            int sB = row_start_sh[rowB], enB = row_start_sh[rowB + 1];
            for (int k = sB; k < enB; ++k) {
                int u = mu1_sh[k], v = mu2_sh[k];
                float c = cg_sh[k];
                for (int j = 0; j < ng; ++j) {
                    if (uA[j] == u) {
                        if (v == m2A[j]) cBa[j] = c; else cBb[j] = c;
                        break;
                    }
                }
            }
        }
        int base = job_off[jid];
        for (int g = 0; g < ng; ++g) {
            cg4_sh[base + g]  = make_float4(cAa[g], cAb[g], cBa[g], cBb[g]);
            pack_sh[base + g] = ((unsigned)(uA[g] * (XPAD * 4)) << 8)
                              | ((unsigned)m2A[g] << 4) | (unsigned)m2B[g];
        }
        g_job_info[jid]  = m | (rowB << 8) | (p << 16);
        g_job_start[jid] = base;
    }
    __syncthreads();

    // copy group tables to global (+ zero pad entry for the lookahead)
    {
        const int npg = job_off[njobs];
        for (int j = t; j < npg; j += blockDim.x) {
            g_cg4[j]  = cg4_sh[j];
            g_pack[j] = pack_sh[j];
        }
        if (t == 0) {
            g_cg4[npg]  = make_float4(0.f, 0.f, 0.f, 0.f);
            g_pack[npg] = 0u;
            g_job_start[njobs] = npg;
            g_counts = make_int2(njobs, npg);
        }
    }

    // rank jobs by group count desc (stable) -> schedule
    for (int j = t; j < njobs; j += blockDim.x) {
        const int lj = job_cnt[j];
        int rank = 0;
        for (int o = 0; o < njobs; ++o) {
            int lo_ = job_cnt[o];
            rank += (lo_ > lj) || (lo_ == lj && o < j);
        }
        g_job_order[rank] = j;
    }

    __syncthreads();
    cudaTriggerProgrammaticLaunchCompletion();
}

// One block per edge, 256 threads: q = tid&3 -> channel quad, r = tid>>2 -> slot.
// Each slot processes a JOB = fused (+m,-m) row pair: per pair-group one
// LDS.128 ent {cgyA,cgyB,xoff} + one ld.shared.v2.u64 x row feeds BOTH rows
// (4 packed FMAs -> 8 output floats). PDL preamble overlaps prep.
__global__ void __launch_bounds__(256)
tp_main_kernel(const float* __restrict__ x,
               const float* __restrict__ y,
               float* __restrict__ out,
               int dim3v) {
    __shared__ __align__(16) float  x_sh[DIM_IN * XPAD];
    __shared__ __align__(16) float4 ent_sh[MAX_GRP + 1];
    __shared__ float y_sh[DIM_IN];

    const int e = blockIdx.x;
    const int t = threadIdx.x;

    // ---- preamble (independent of prep outputs) ----
    {
        float v = x[e * (DIM_IN * C_DIM) + t];
        x_sh[(t >> 4) * XPAD + (t & 15)] = v;
        if (t < DIM_IN) y_sh[t] = y[e * DIM_IN + t];
    }

    cudaGridDependencySynchronize();       // wait for prep's global writes
    __syncthreads();

    const int2 counts = g_counts;
    const int njobs = counts.x;
    const int npg   = counts.y;

    // per-edge pair-group table (+ pad entry for lookahead)
    for (int j = t; j <= npg; j += 256) {
        float4 c4 = g_cg4[j];
        unsigned pk = g_pack[j];
        float ya = y_sh[(pk >> 4) & 15u];
        float yb = y_sh[pk & 15u];
        float cgyA = c4.x * ya + c4.y * yb;
        float cgyB = c4.z * ya + c4.w * yb;
        ent_sh[j] = make_float4(cgyA, cgyB, __uint_as_float(pk >> 8), 0.f);
    }
    __syncthreads();

    const int q = t & 3;          // channel quad
    const int r = t >> 2;         // schedule slot 0..63
    const unsigned xq = s2u(x_sh) + (unsigned)(q * 16);
    float* outE = out + (size_t)e * dim3v * C_DIM;

    for (int i = r; i < njobs; i += 64) {
        const int jid  = g_job_order[i];
        const int info = g_job_info[jid];
        const int s  = g_job_start[jid];
        const int en = g_job_start[jid + 1];

        unsigned long long aA01 = 0ull, aA23 = 0ull;
        unsigned long long aB01 = 0ull, aB23 = 0ull;
        float4 ent = ent_sh[s];
        #pragma unroll 2
        for (int k = s; k < en; ++k) {
            float4 ent_n = ent_sh[k + 1];            // lookahead (pad-safe)
            unsigned long long x01, x23, cA2, cB2;
            asm volatile("ld.shared.v2.u64 {%0,%1},[%2];"
                         : "=l"(x01), "=l"(x23)
                         : "r"(xq + __float_as_uint(ent.z)));
            asm("mov.b64 %0,{%1,%1};" : "=l"(cA2) : "f"(ent.x));
            asm("mov.b64 %0,{%1,%1};" : "=l"(cB2) : "f"(ent.y));
            asm("fma.rn.f32x2 %0,%1,%2,%0;" : "+l"(aA01) : "l"(x01), "l"(cA2));
            asm("fma.rn.f32x2 %0,%1,%2,%0;" : "+l"(aA23) : "l"(x23), "l"(cA2));
            asm("fma.rn.f32x2 %0,%1,%2,%0;" : "+l"(aB01) : "l"(x01), "l"(cB2));
            asm("fma.rn.f32x2 %0,%1,%2,%0;" : "+l"(aB23) : "l"(x23), "l"(cB2));
            ent = ent_n;
        }

        const int rowA = info & 255;
        const int rowB = (info >> 8) & 255;
        const int path = info >> 16;
        const float4 wv = *(const float4*)(g_wT + path * C_DIM + q * 4);
        unsigned long long w01, w23;
        asm("mov.b64 %0,{%1,%2};" : "=l"(w01) : "f"(wv.x), "f"(wv.y));
        asm("mov.b64 %0,{%1,%2};" : "=l"(w23) : "f"(wv.z), "f"(wv.w));
        asm("mul.rn.f32x2 %0,%0,%1;" : "+l"(aA01) : "l"(w01));
        asm("mul.rn.f32x2 %0,%0,%1;" : "+l"(aA23) : "l"(w23));

        float* dstA = outE + rowA * C_DIM + q * 4;
        asm volatile("st.global.cs.v2.u64 [%0],{%1,%2};"
                     :: "l"(dstA), "l"(aA01), "l"(aA23) : "memory");
        if (rowB != rowA) {
            asm("mul.rn.f32x2 %0,%0,%1;" : "+l"(aB01) : "l"(w01));
            asm("mul.rn.f32x2 %0,%0,%1;" : "+l"(aB23) : "l"(w23));
            float* dstB = outE + rowB * C_DIM + q * 4;
            asm volatile("st.global.cs.v2.u64 [%0],{%1,%2};"
                         :: "l"(dstB), "l"(aB01), "l"(aB23) : "memory");
        }
    }
}

extern "C" void kernel_launch(void* const* d_in, const int* in_sizes, int n_in,
                              void* d_out, int out_size) {
    const float* x      = (const float*)d_in[0];
    const float* y      = (const float*)d_in[1];
    const float* cg     = (const float*)d_in[2];
    const float* w      = (const float*)d_in[3];
    const int*   mu1    = (const int*)d_in[4];
    const int*   mu2    = (const int*)d_in[5];
    const int*   mu3    = (const int*)d_in[6];
    const int*   widx   = (const int*)d_in[7];

    const int nnz     = in_sizes[4];
    const int E       = in_sizes[1] / DIM_IN;
    const int dim3v   = out_size / (E * C_DIM);
    const int n_paths = in_sizes[3] / C_DIM;

    tp_prep_kernel<<<1, 256>>>(w, cg, mu1, mu2, mu3, widx, nnz, dim3v, n_paths);

    // Programmatic Dependent Launch: main's grid ramp + x/y staging overlap
    // the prep kernel's tail
    cudaLaunchConfig_t cfg = {};
    cfg.gridDim  = dim3(E);
    cfg.blockDim = dim3(256);
    cudaLaunchAttribute attrs[1];
    attrs[0].id = cudaLaunchAttributeProgrammaticStreamSerialization;
    attrs[0].val.programmaticStreamSerializationAllowed = 1;
    cfg.attrs = attrs;
    cfg.numAttrs = 1;
    cudaLaunchKernelEx(&cfg, tp_main_kernel, x, y, (float*)d_out, dim3v);
}

// round 17
// speedup vs baseline: 1.3136x; 1.0625x over previous
#include <cuda_runtime.h>

#define C_DIM    16
#define DIM_IN   16
#define XPAD     20          // floats per mu1 row in shared (80B stride, 16B-aligned)
#define MAX_NNZ  1024
#define MAX_GRP  1024
#define MAX_ROWS 256
#define MAX_JOBS 160
#define MAX_PATHS 64
#define TPB      384         // 96 slots x 4 channel-quads; njobs=95 -> 1 job/slot

// job = fused (+m, -m) row pair within a path (or m=0 singleton).
// g_job_meta is stored in LENGTH-SORTED order: {grp_start, grp_end, info, 0}
__device__ __align__(16) int4 g_job_meta[MAX_JOBS];
__device__ int2  g_counts;                    // {njobs, n_pair_groups}
__device__ __align__(16) float  g_wT[MAX_PATHS * C_DIM];
// pair-group statics: cg4 = {cgA_a, cgA_b, cgB_a, cgB_b},
// pack = (mu1*80)<<8 | m2a<<4 | m2b   (unused slots have cg = 0)
__device__ __align__(16) float4   g_cg4[MAX_GRP + 1];
__device__ unsigned g_pack[MAX_GRP + 1];

__device__ __forceinline__ unsigned s2u(const void* p) {
    return (unsigned)__cvta_generic_to_shared(p);
}

// Prep (one block, 256 threads). Builds the paired-row job structure and
// emits job metadata PRE-SORTED by group count (desc) so the main kernel
// reads one int4 per slot with no indirection.
__global__ void tp_prep_kernel(const float* __restrict__ weights,
                               const float* __restrict__ cg,
                               const int* __restrict__ mu1,
                               const int* __restrict__ mu2,
                               const int* __restrict__ mu3,
                               const int* __restrict__ widx,
                               int nnz, int dim3v, int n_paths) {
    __shared__ short mu1_sh[MAX_NNZ];
    __shared__ short mu2_sh[MAX_NNZ];
    __shared__ float cg_sh[MAX_NNZ];
    __shared__ int row_start_sh[MAX_ROWS + 1];
    __shared__ int row_path_sh[MAX_ROWS];
    __shared__ int path_first_sh[MAX_PATHS + 1];
    __shared__ int jobid_sh[MAX_ROWS];        // job id per leader row
    __shared__ int job_cnt[MAX_JOBS];
    __shared__ int job_off[MAX_JOBS + 1];
    __shared__ int job_info_sh[MAX_JOBS];
    __shared__ int job_rank_sh[MAX_JOBS];
    __shared__ int njobs_sh;
    __shared__ __align__(16) float4   cg4_sh[MAX_GRP];
    __shared__ unsigned pack_sh[MAX_GRP];
    const int t = threadIdx.x;

    // stage + detect row AND path boundaries in one pass (mu3 sorted, widx
    // blocks contiguous)
    for (int k = t; k < nnz; k += blockDim.x) {
        mu1_sh[k] = (short)mu1[k];
        mu2_sh[k] = (short)mu2[k];
        cg_sh[k]  = cg[k];
        int m = mu3[k];
        int p = widx[k];
        if (k == 0 || mu3[k - 1] != m) {
            row_start_sh[m] = k;
            row_path_sh[m] = p;
            if (k == 0 || widx[k - 1] != p) path_first_sh[p] = m;
        }
    }
    for (int i = t; i < n_paths * C_DIM; i += blockDim.x) {
        int p = i >> 4, c = i & 15;
        g_wT[p * C_DIM + c] = weights[c * n_paths + p];
    }
    if (t == 0) {
        row_start_sh[dim3v] = nnz;
        path_first_sh[n_paths] = dim3v;
    }
    __syncthreads();

    // leader flags (row is job leader if its in-path index i <= d3-1-i) and
    // exclusive scan -> job ids (warp 0)
    if (t < 32) {
        int nchunk = (dim3v + 31) >> 5;
        int carry = 0;
        for (int cch = 0; cch < nchunk; ++cch) {
            int idx = (cch << 5) + t;
            int f = 0;
            if (idx < dim3v) {
                int p = row_path_sh[idx];
                int pf = path_first_sh[p];
                int d3 = path_first_sh[p + 1] - pf;
                f = (2 * (idx - pf) <= d3 - 1);
            }
            int v = f;
            #pragma unroll
            for (int d = 1; d < 32; d <<= 1) {
                int n = __shfl_up_sync(0xffffffffu, v, d);
                if (t >= d) v += n;
            }
            if (idx < dim3v) jobid_sh[idx] = (carry + v - f) | (f ? 0 : 0x40000000);
            carry += __shfl_sync(0xffffffffu, v, 31);
        }
        if (t == 0) njobs_sh = carry;
    }
    __syncthreads();
    const int njobs = njobs_sh;

    // count unique mu1 per leader row -> job group counts
    for (int m = t; m < dim3v; m += blockDim.x) {
        int jid = jobid_sh[m];
        if (jid & 0x40000000) continue;               // not a leader
        int s = row_start_sh[m], en = row_start_sh[m + 1];
        int seen[8]; int ng = 0;
        for (int k = s; k < en; ++k) {
            int u = mu1_sh[k];
            bool dup = false;
            for (int j = 0; j < ng; ++j) if (seen[j] == u) { dup = true; break; }
            if (!dup) seen[ng++] = u;
        }
        job_cnt[jid] = ng;
    }
    __syncthreads();

    // exclusive scan of job_cnt (warp 0)
    if (t < 32) {
        int nchunk = (njobs + 31) >> 5;
        int carry = 0;
        for (int cch = 0; cch < nchunk; ++cch) {
            int idx = (cch << 5) + t;
            int v = (idx < njobs) ? job_cnt[idx] : 0;
            #pragma unroll
            for (int d = 1; d < 32; d <<= 1) {
                int n = __shfl_up_sync(0xffffffffu, v, d);
                if (t >= d) v += n;
            }
            if (idx < njobs) job_off[idx] = carry + v - job_cnt[idx];
            carry += __shfl_sync(0xffffffffu, v, 31);
        }
        if (t == 0) job_off[njobs] = carry;
    }
    __syncthreads();

    // emit pair-groups (rowA builds slots, rowB's cgs matched in) and,
    // in the same phase, compute each job's sorted rank (needs job_cnt only)
    for (int m = t; m < dim3v; m += blockDim.x) {
        int jid = jobid_sh[m];
        if (jid & 0x40000000) continue;
        int p  = row_path_sh[m];
        int pf = path_first_sh[p];
        int d3 = path_first_sh[p + 1] - pf;
        int rowB = pf + (d3 - 1) - (m - pf);
        int s = row_start_sh[m], en = row_start_sh[m + 1];

        short uA[8], m2A[8], m2B[8];
        float cAa[8], cAb[8], cBa[8], cBb[8];
        int ng = 0;
        for (int k = s; k < en; ++k) {
            int u = mu1_sh[k], v = mu2_sh[k];
            float c = cg_sh[k];
            int g = -1;
            for (int j = 0; j < ng; ++j) if (uA[j] == u) { g = j; break; }
            if (g < 0) {
                g = ng++;
                uA[g] = (short)u; m2A[g] = (short)v; m2B[g] = 0;
                cAa[g] = c; cAb[g] = 0.f; cBa[g] = 0.f; cBb[g] = 0.f;
            } else {
                m2B[g] = (short)v; cAb[g] = c;
            }
        }
        if (rowB != m) {
            int sB = row_start_sh[rowB], enB = row_start_sh[rowB + 1];
            for (int k = sB; k < enB; ++k) {
                int u = mu1_sh[k], v = mu2_sh[k];
                float c = cg_sh[k];
                for (int j = 0; j < ng; ++j) {
                    if (uA[j] == u) {
                        if (v == m2A[j]) cBa[j] = c; else cBb[j] = c;
                        break;
                    }
                }
            }
        }
        int base = job_off[jid];
        for (int g = 0; g < ng; ++g) {
            cg4_sh[base + g]  = make_float4(cAa[g], cAb[g], cBa[g], cBb[g]);
            pack_sh[base + g] = ((unsigned)(uA[g] * (XPAD * 4)) << 8)
                              | ((unsigned)m2A[g] << 4) | (unsigned)m2B[g];
        }
        job_info_sh[jid] = m | (rowB << 8) | (p << 16);
    }
    // rank = #jobs with strictly more groups (ties by id) -> stable desc
    for (int j = t; j < njobs; j += blockDim.x) {
        const int lj = job_cnt[j];
        int rank = 0;
        for (int o = 0; o < njobs; ++o) {
            int lo_ = job_cnt[o];
            rank += (lo_ > lj) || (lo_ == lj && o < j);
        }
        job_rank_sh[j] = rank;
    }
    __syncthreads();

    // copy group tables to global (+ zero pad entry) and scatter SORTED metas
    {
        const int npg = job_off[njobs];
        for (int j = t; j < npg; j += blockDim.x) {
            g_cg4[j]  = cg4_sh[j];
            g_pack[j] = pack_sh[j];
        }
        for (int j = t; j < njobs; j += blockDim.x) {
            g_job_meta[job_rank_sh[j]] =
                make_int4(job_off[j], job_off[j] + job_cnt[j], job_info_sh[j], 0);
        }
        if (t == 0) {
            g_cg4[npg]  = make_float4(0.f, 0.f, 0.f, 0.f);
            g_pack[npg] = 0u;
            g_counts = make_int2(njobs, npg);
        }
    }

    __syncthreads();
    cudaTriggerProgrammaticLaunchCompletion();
}

// One block per edge, 384 threads = 96 slots x 4 channel-quads. njobs=95 so
// each slot owns at most ONE job (perfectly balanced, no second pass); job
// metadata is a single independent LDG.128. Per pair-group: one LDS.128 ent
// {cgyA,cgyB,xoff} + one ld.shared.v2.u64 x row feeds BOTH rows of the pair
// (4 packed FMAs -> 8 output floats). PDL preamble overlaps prep.
__global__ void __launch_bounds__(TPB)
tp_main_kernel(const float* __restrict__ x,
               const float* __restrict__ y,
               float* __restrict__ out,
               int dim3v) {
    __shared__ __align__(16) float  x_sh[DIM_IN * XPAD];
    __shared__ __align__(16) float4 ent_sh[MAX_GRP + 1];
    __shared__ float y_sh[DIM_IN];

    const int e = blockIdx.x;
    const int t = threadIdx.x;

    // ---- preamble (independent of prep outputs) ----
    if (t < DIM_IN * C_DIM) {
        float v = x[e * (DIM_IN * C_DIM) + t];
        x_sh[(t >> 4) * XPAD + (t & 15)] = v;
    }
    if (t < DIM_IN) y_sh[t] = y[e * DIM_IN + t];

    cudaGridDependencySynchronize();       // wait for prep's global writes
    __syncthreads();

    const int2 counts = g_counts;
    const int njobs = counts.x;
    const int npg   = counts.y;

    // per-edge pair-group table (+ pad entry for lookahead)
    for (int j = t; j <= npg; j += TPB) {
        float4 c4 = g_cg4[j];
        unsigned pk = g_pack[j];
        float ya = y_sh[(pk >> 4) & 15u];
        float yb = y_sh[pk & 15u];
        float cgyA = c4.x * ya + c4.y * yb;
        float cgyB = c4.z * ya + c4.w * yb;
        ent_sh[j] = make_float4(cgyA, cgyB, __uint_as_float(pk >> 8), 0.f);
    }
    __syncthreads();

    const int q = t & 3;          // channel quad
    const int slot = t >> 2;      // 0..95
    const unsigned xq = s2u(x_sh) + (unsigned)(q * 16);
    float* outE = out + (size_t)e * dim3v * C_DIM;

    for (int i = slot; i < njobs; i += TPB / 4) {   // 1 iteration when njobs<=96
        const int4 meta = g_job_meta[i];            // {start, end, info, 0}
        const int s    = meta.x;
        const int en   = meta.y;
        const int info = meta.z;

        unsigned long long aA01 = 0ull, aA23 = 0ull;
        unsigned long long aB01 = 0ull, aB23 = 0ull;
        float4 ent = ent_sh[s];
        #pragma unroll 2
        for (int k = s; k < en; ++k) {
            float4 ent_n = ent_sh[k + 1];            // lookahead (pad-safe)
            unsigned long long x01, x23, cA2, cB2;
            asm volatile("ld.shared.v2.u64 {%0,%1},[%2];"
                         : "=l"(x01), "=l"(x23)
                         : "r"(xq + __float_as_uint(ent.z)));
            asm("mov.b64 %0,{%1,%1};" : "=l"(cA2) : "f"(ent.x));
            asm("mov.b64 %0,{%1,%1};" : "=l"(cB2) : "f"(ent.y));
            asm("fma.rn.f32x2 %0,%1,%2,%0;" : "+l"(aA01) : "l"(x01), "l"(cA2));
            asm("fma.rn.f32x2 %0,%1,%2,%0;" : "+l"(aA23) : "l"(x23), "l"(cA2));
            asm("fma.rn.f32x2 %0,%1,%2,%0;" : "+l"(aB01) : "l"(x01), "l"(cB2));
            asm("fma.rn.f32x2 %0,%1,%2,%0;" : "+l"(aB23) : "l"(x23), "l"(cB2));
            ent = ent_n;
        }

        const int rowA = info & 255;
        const int rowB = (info >> 8) & 255;
        const int path = info >> 16;
        const float4 wv = *(const float4*)(g_wT + path * C_DIM + q * 4);
        unsigned long long w01, w23;
        asm("mov.b64 %0,{%1,%2};" : "=l"(w01) : "f"(wv.x), "f"(wv.y));
        asm("mov.b64 %0,{%1,%2};" : "=l"(w23) : "f"(wv.z), "f"(wv.w));
        asm("mul.rn.f32x2 %0,%0,%1;" : "+l"(aA01) : "l"(w01));
        asm("mul.rn.f32x2 %0,%0,%1;" : "+l"(aA23) : "l"(w23));

        float* dstA = outE + rowA * C_DIM + q * 4;
        asm volatile("st.global.cs.v2.u64 [%0],{%1,%2};"
                     :: "l"(dstA), "l"(aA01), "l"(aA23) : "memory");
        if (rowB != rowA) {
            asm("mul.rn.f32x2 %0,%0,%1;" : "+l"(aB01) : "l"(w01));
            asm("mul.rn.f32x2 %0,%0,%1;" : "+l"(aB23) : "l"(w23));
            float* dstB = outE + rowB * C_DIM + q * 4;
            asm volatile("st.global.cs.v2.u64 [%0],{%1,%2};"
                         :: "l"(dstB), "l"(aB01), "l"(aB23) : "memory");
        }
    }
}

extern "C" void kernel_launch(void* const* d_in, const int* in_sizes, int n_in,
                              void* d_out, int out_size) {
    const float* x      = (const float*)d_in[0];
    const float* y      = (const float*)d_in[1];
    const float* cg     = (const float*)d_in[2];
    const float* w      = (const float*)d_in[3];
    const int*   mu1    = (const int*)d_in[4];
    const int*   mu2    = (const int*)d_in[5];
    const int*   mu3    = (const int*)d_in[6];
    const int*   widx   = (const int*)d_in[7];

    const int nnz     = in_sizes[4];
    const int E       = in_sizes[1] / DIM_IN;
    const int dim3v   = out_size / (E * C_DIM);
    const int n_paths = in_sizes[3] / C_DIM;

    tp_prep_kernel<<<1, 256>>>(w, cg, mu1, mu2, mu3, widx, nnz, dim3v, n_paths);

    // Programmatic Dependent Launch: main's grid ramp + x/y staging overlap
    // the prep kernel's tail
    cudaLaunchConfig_t cfg = {};
    cfg.gridDim  = dim3(E);
    cfg.blockDim = dim3(TPB);
    cudaLaunchAttribute attrs[1];
    attrs[0].id = cudaLaunchAttributeProgrammaticStreamSerialization;
    attrs[0].val.programmaticStreamSerializationAllowed = 1;
    cfg.attrs = attrs;
    cfg.numAttrs = 1;
    cudaLaunchKernelEx(&cfg, tp_main_kernel, x, y, (float*)d_out, dim3v);
}